// round 1
// baseline (speedup 1.0000x reference)
#include <cuda_runtime.h>
#include <cstdint>

#define N_NODES 200000
#define DEG 16
#define T_ROUNDS 3
#define HDIM 70
#define HSTRIDE 72          // padded row stride for h buffers (16B-aligned rows)
#define KTOT 146            // 70 (self) + 70 (gathered) + 6 (edge msg)
#define BM 64               // nodes per block tile
#define BN 72               // output cols per block tile (70 padded to 72)
#define TY 16
#define TX 18
#define NTHR (TY*TX)        // 288 threads
#define XSTR 68             // padded Xs row stride (68*4=272B, 16B aligned, low-conflict)
#define NBLK (N_NODES/BM)   // 3125 exactly

#define RBLOCKS 1024
#define RTHREADS 128

// -------- device scratch (static globals: no runtime allocation) --------
__device__ float g_h[2][N_NODES * HSTRIDE];      // ping-pong node states
__device__ float g_me6[N_NODES * DEG * 6];       // precomputed E(e) messages
__device__ float g_Wcat[KTOT * BN];              // [U1 ; Vw@U2 ; U3], padded cols
__device__ float g_btot[BN];                     // Ub + Vb@U2, padded
__device__ float g_Rc[HDIM * 128];               // Rw[:70] + Rw[70:140]
__device__ float g_partial[RBLOCKS * 128];       // readout partial sums

// -------- one-time (per replay) weight folding --------
__global__ void prep_kernel(const float* __restrict__ Vw, const float* __restrict__ Vb,
                            const float* __restrict__ Uw, const float* __restrict__ Ub,
                            const float* __restrict__ Rw) {
    int tid = threadIdx.x;
    for (int i = tid; i < KTOT * BN; i += blockDim.x) {
        int r = i / BN, k = i % BN;
        float v = 0.f;
        if (k < HDIM) {
            if (r < 70) {
                v = Uw[r * HDIM + k];
            } else if (r < 140) {
                int p = r - 70;
                float s = 0.f;
                for (int q = 0; q < 70; ++q)
                    s += Vw[p * 70 + q] * Uw[(70 + q) * HDIM + k];
                v = s;
            } else {
                v = Uw[r * HDIM + k];
            }
        }
        g_Wcat[i] = v;
    }
    for (int k = tid; k < BN; k += blockDim.x) {
        float v = 0.f;
        if (k < HDIM) {
            v = Ub[k];
            for (int q = 0; q < 70; ++q)
                v += Vb[q] * Uw[(70 + q) * HDIM + k];
        }
        g_btot[k] = v;
    }
    for (int i = tid; i < HDIM * 128; i += blockDim.x) {
        int p = i / 128, k = i % 128;
        g_Rc[i] = Rw[p * 128 + k] + Rw[(70 + p) * 128 + k];
    }
}

// -------- precompute edge messages m_e = e @ Ew + Eb  (h-independent) --------
__global__ void edge_kernel(const float* __restrict__ ef,
                            const float* __restrict__ Ew,
                            const float* __restrict__ Eb) {
    int i = blockIdx.x * blockDim.x + threadIdx.x;   // (node, slot) flat index
    if (i >= N_NODES * DEG) return;
    float e[6];
#pragma unroll
    for (int d = 0; d < 6; ++d) e[d] = ef[i * 6 + d];
#pragma unroll
    for (int c = 0; c < 6; ++c) {
        float s = __ldg(&Eb[c]);
#pragma unroll
        for (int d = 0; d < 6; ++d) s += e[d] * __ldg(&Ew[d * 6 + c]);
        g_me6[i * 6 + c] = s;
    }
}

// -------- copy input h into padded ping-pong buffer 0 --------
__global__ void init_kernel(const float* __restrict__ h) {
    int i = blockIdx.x * blockDim.x + threadIdx.x;
    if (i >= N_NODES * HSTRIDE) return;
    int v = i / HSTRIDE, k = i % HSTRIDE;
    g_h[0][i] = (k < HDIM) ? h[v * HDIM + k] : 0.f;
}

// -------- one message-passing step: h' = relu([h | h[idx] | me6] @ Wcat + btot) --------
__global__ __launch_bounds__(NTHR, 2)
void step_kernel(const int* __restrict__ nbr, int j, int src) {
    extern __shared__ float sm[];
    float* Ws = sm;                   // KTOT*BN
    float* Xs = sm + KTOT * BN;       // KTOT*XSTR, transposed X tile
    __shared__ __align__(16) float bts[BN];
    __shared__ int gidx[BM];

    const float* __restrict__ hin = g_h[src];
    float* __restrict__ hout = g_h[src ^ 1];
    int tid = threadIdx.x;
    int base = blockIdx.x * BM;

    for (int i = tid; i < KTOT * BN; i += NTHR) Ws[i] = g_Wcat[i];
    if (tid < BN) bts[tid] = g_btot[tid];
    if (tid < BM) gidx[tid] = nbr[(base + tid) * DEG + j];
    __syncthreads();

    // fill transposed X tile: rows 0..69 self, 70..139 gathered, 140..145 edge msg
    for (int i = tid; i < BM * HDIM; i += NTHR) {
        int m = i / HDIM, k = i % HDIM;
        Xs[k * XSTR + m] = hin[(base + m) * HSTRIDE + k];
    }
    for (int i = tid; i < BM * HDIM; i += NTHR) {
        int m = i / HDIM, k = i % HDIM;
        Xs[(HDIM + k) * XSTR + m] = hin[gidx[m] * HSTRIDE + k];
    }
    for (int i = tid; i < BM * 6; i += NTHR) {
        int m = i / 6, c = i % 6;
        Xs[(140 + c) * XSTR + m] = g_me6[((base + m) * DEG + j) * 6 + c];
    }
    __syncthreads();

    int tx = tid % TX, ty = tid / TX;
    int col0 = tx * 4, row0 = ty * 4;
    float acc[4][4];
#pragma unroll
    for (int a = 0; a < 4; ++a)
#pragma unroll
        for (int b = 0; b < 4; ++b) acc[a][b] = 0.f;

    const float* xp = Xs + row0;
    const float* wp = Ws + col0;
#pragma unroll 2
    for (int k = 0; k < KTOT; ++k) {
        float4 av = *(const float4*)(xp + k * XSTR);
        float4 wv = *(const float4*)(wp + k * BN);
        acc[0][0] += av.x * wv.x; acc[0][1] += av.x * wv.y;
        acc[0][2] += av.x * wv.z; acc[0][3] += av.x * wv.w;
        acc[1][0] += av.y * wv.x; acc[1][1] += av.y * wv.y;
        acc[1][2] += av.y * wv.z; acc[1][3] += av.y * wv.w;
        acc[2][0] += av.z * wv.x; acc[2][1] += av.z * wv.y;
        acc[2][2] += av.z * wv.z; acc[2][3] += av.z * wv.w;
        acc[3][0] += av.w * wv.x; acc[3][1] += av.w * wv.y;
        acc[3][2] += av.w * wv.z; acc[3][3] += av.w * wv.w;
    }

    float4 bt = *(const float4*)(bts + col0);
#pragma unroll
    for (int m = 0; m < 4; ++m) {
        float4 o;
        o.x = fmaxf(acc[m][0] + bt.x, 0.f);
        o.y = fmaxf(acc[m][1] + bt.y, 0.f);
        o.z = fmaxf(acc[m][2] + bt.z, 0.f);
        o.w = fmaxf(acc[m][3] + bt.w, 0.f);
        *(float4*)(hout + (base + row0 + m) * HSTRIDE + col0) = o;  // cols 70/71 write clean 0
    }
}

// -------- readout: partial_b[k] = sum_{nodes in b} relu(h @ Rc + Rb)[k] --------
__global__ __launch_bounds__(RTHREADS)
void readout_kernel(const float* __restrict__ Rb) {
    int k = threadIdx.x;             // output feature 0..127
    float rc[HSTRIDE];
#pragma unroll
    for (int p = 0; p < HDIM; ++p) rc[p] = g_Rc[p * 128 + k];
    rc[70] = 0.f; rc[71] = 0.f;
    float rb = Rb[k];

    int per = (N_NODES + RBLOCKS - 1) / RBLOCKS;
    int n0 = blockIdx.x * per;
    int n1 = n0 + per; if (n1 > N_NODES) n1 = N_NODES;

    float acc = 0.f;
    for (int n = n0; n < n1; ++n) {
        const float4* hp = (const float4*)(g_h[0] + n * HSTRIDE);
        float s = rb;
#pragma unroll
        for (int q = 0; q < HSTRIDE / 4; ++q) {
            float4 hv = __ldg(&hp[q]);
            s += hv.x * rc[4 * q] + hv.y * rc[4 * q + 1]
               + hv.z * rc[4 * q + 2] + hv.w * rc[4 * q + 3];
        }
        acc += fmaxf(s, 0.f);
    }
    g_partial[blockIdx.x * 128 + k] = acc;
}

// -------- deterministic reduction + head MLP, single block --------
__global__ void final_kernel(const float* __restrict__ S1w, const float* __restrict__ S1b,
                             const float* __restrict__ S2w, const float* __restrict__ S2b,
                             const float* __restrict__ Hw,  const float* __restrict__ Hb,
                             const float* __restrict__ Ow,  const float* __restrict__ Ob,
                             float* __restrict__ out) {
    __shared__ float fm[128], av[128], bv[100], cv[100];
    int t = threadIdx.x;   // 128 threads
    float s = 0.f;
    for (int b = 0; b < RBLOCKS; ++b) s += g_partial[b * 128 + t];
    fm[t] = s;
    __syncthreads();
    float v = S1b[t];
    for (int p = 0; p < 128; ++p) v += fm[p] * S1w[p * 128 + t];
    av[t] = fmaxf(v, 0.f);
    __syncthreads();
    if (t < 100) {
        v = S2b[t];
        for (int p = 0; p < 128; ++p) v += av[p] * S2w[p * 100 + t];
        bv[t] = v;
    }
    __syncthreads();
    if (t < 100) {
        v = Hb[t];
        for (int p = 0; p < 100; ++p) v += bv[p] * Hw[p * 100 + t];
        cv[t] = fmaxf(v, 0.f);
    }
    __syncthreads();
    if (t == 0) {
        v = Ob[0];
        for (int p = 0; p < 100; ++p) v += cv[p] * Ow[p];
        out[0] = v;
    }
}

extern "C" void kernel_launch(void* const* d_in, const int* in_sizes, int n_in,
                              void* d_out, int out_size) {
    const float* h   = (const float*)d_in[0];
    const float* ef  = (const float*)d_in[1];
    const int*   nbr = (const int*)d_in[2];
    const float* Vw  = (const float*)d_in[3];
    const float* Vb  = (const float*)d_in[4];
    const float* Ew  = (const float*)d_in[5];
    const float* Eb  = (const float*)d_in[6];
    const float* Uw  = (const float*)d_in[7];
    const float* Ub  = (const float*)d_in[8];
    const float* Rw  = (const float*)d_in[9];
    const float* Rb  = (const float*)d_in[10];
    const float* S1w = (const float*)d_in[11];
    const float* S1b = (const float*)d_in[12];
    const float* S2w = (const float*)d_in[13];
    const float* S2b = (const float*)d_in[14];
    const float* Hw  = (const float*)d_in[15];
    const float* Hb  = (const float*)d_in[16];
    const float* Ow  = (const float*)d_in[17];
    const float* Ob  = (const float*)d_in[18];
    float* out = (float*)d_out;

    const int SMEM = (KTOT * BN + KTOT * XSTR) * 4;   // 81760 bytes
    cudaFuncSetAttribute(step_kernel, cudaFuncAttributeMaxDynamicSharedMemorySize, SMEM);

    prep_kernel<<<1, 256>>>(Vw, Vb, Uw, Ub, Rw);
    edge_kernel<<<(N_NODES * DEG + 255) / 256, 256>>>(ef, Ew, Eb);
    init_kernel<<<(N_NODES * HSTRIDE + 255) / 256, 256>>>(h);

    int src = 0;
    for (int r = 0; r < T_ROUNDS; ++r) {
        for (int j = 0; j < DEG; ++j) {
            step_kernel<<<NBLK, NTHR, SMEM>>>(nbr, j, src);
            src ^= 1;
        }
    }
    // 48 steps (even) -> final state is in g_h[0]
    readout_kernel<<<RBLOCKS, RTHREADS>>>(Rb);
    final_kernel<<<1, 128>>>(S1w, S1b, S2w, S2b, Hw, Hb, Ow, Ob, out);
}

// round 3
// speedup vs baseline: 1.2898x; 1.2898x over previous
#include <cuda_runtime.h>
#include <cstdint>

#define N_NODES 200000
#define DEG 16
#define T_ROUNDS 3
#define HDIM 70
#define HSTRIDE 72
#define NKT 19              // 152 = 19 * 8 K-slots
#define KPAD 152
#define NB 72               // padded N
#define WARPS 9
#define THREADS 288
#define BMT 8               // m-tiles (16 nodes) per block
#define BM 128              // nodes per block
#define ASTRIDE 164         // smem row stride in 32-bit words (164 mod 32 == 4 -> conflict-free frags)
#define NBLK ((N_NODES + BM - 1) / BM)   // 1563

#define RBLOCKS 1024
#define RTHREADS 128

// ---------------- device scratch (static: no allocation) ----------------
__device__ float    g_h[2][N_NODES * HSTRIDE];
__device__ float    g_me6[N_NODES * DEG * 6];
__device__ float    g_Wtmp[KPAD * NB];
__device__ uint32_t g_Bfhi[WARPS * NKT * 2 * 32];   // B fragments, mma order, tf32 hi
__device__ uint32_t g_Bflo[WARPS * NKT * 2 * 32];   // tf32 lo
__device__ float    g_btot[NB];
__device__ float    g_Rc[HDIM * 128];
__device__ float    g_partial[RBLOCKS * 128];

// ---------------- helpers ----------------
__device__ __forceinline__ uint32_t cvt_tf32(float x) {
    uint32_t r;
    asm("cvt.rn.tf32.f32 %0, %1;" : "=r"(r) : "f"(x));
    return r;
}

#define MMA4(c0,c1,c2,c3,a0,a1,a2,a3,b0,b1)                                  \
    asm volatile("mma.sync.aligned.m16n8k8.row.col.f32.tf32.tf32.f32 "       \
        "{%0,%1,%2,%3}, {%4,%5,%6,%7}, {%8,%9}, {%0,%1,%2,%3};"              \
        : "+f"(c0), "+f"(c1), "+f"(c2), "+f"(c3)                             \
        : "r"(a0), "r"(a1), "r"(a2), "r"(a3), "r"(b0), "r"(b1))

// ---------------- weight folding -> mma-fragment images ----------------
// K-slot map: k in [0,70)=U1 ; [72,142)=(Vw@U2) ; [144,150)=U3 ; else 0.
__global__ void prep_kernel(const float* __restrict__ Vw, const float* __restrict__ Vb,
                            const float* __restrict__ Uw, const float* __restrict__ Ub,
                            const float* __restrict__ Rw) {
    int tid = threadIdx.x;
    for (int i = tid; i < KPAD * NB; i += blockDim.x) {
        int k = i / NB, n = i % NB;
        float w = 0.f;
        if (n < HDIM) {
            if (k < 70) {
                w = Uw[k * HDIM + n];
            } else if (k >= 72 && k < 142) {
                int p = k - 72;
                float s = 0.f;
                for (int q = 0; q < 70; ++q) s += Vw[p * 70 + q] * Uw[(70 + q) * HDIM + n];
                w = s;
            } else if (k >= 144 && k < 150) {
                w = Uw[(140 + (k - 144)) * HDIM + n];
            }
        }
        g_Wtmp[i] = w;
    }
    __syncthreads();
    // B fragment order: idx = ((w*NKT + kt)*2 + r)*32 + lane
    // value = W[kt*8 + (lane%4) + 4r][w*8 + lane/4]
    for (int idx = tid; idx < WARPS * NKT * 2 * 32; idx += blockDim.x) {
        int lane = idx & 31;
        int t = idx >> 5;
        int r = t & 1; t >>= 1;
        int kt = t % NKT;
        int w = t / NKT;
        int k = kt * 8 + (lane & 3) + 4 * r;
        int n = w * 8 + (lane >> 2);
        float v = g_Wtmp[k * NB + n];
        uint32_t hi = cvt_tf32(v);
        uint32_t lo = cvt_tf32(v - __uint_as_float(hi));
        g_Bfhi[idx] = hi;
        g_Bflo[idx] = lo;
    }
    for (int k = tid; k < NB; k += blockDim.x) {
        float v = 0.f;
        if (k < HDIM) {
            v = Ub[k];
            for (int q = 0; q < 70; ++q) v += Vb[q] * Uw[(70 + q) * HDIM + k];
        }
        g_btot[k] = v;
    }
    for (int i = tid; i < HDIM * 128; i += blockDim.x) {
        int p = i / 128, k = i % 128;
        g_Rc[i] = Rw[p * 128 + k] + Rw[(70 + p) * 128 + k];
    }
}

// ---------------- edge messages (h-independent, computed once) ----------------
__global__ void edge_kernel(const float* __restrict__ ef,
                            const float* __restrict__ Ew,
                            const float* __restrict__ Eb) {
    int i = blockIdx.x * blockDim.x + threadIdx.x;
    if (i >= N_NODES * DEG) return;
    float e[6];
#pragma unroll
    for (int d = 0; d < 6; ++d) e[d] = ef[i * 6 + d];
#pragma unroll
    for (int c = 0; c < 6; ++c) {
        float s = __ldg(&Eb[c]);
#pragma unroll
        for (int d = 0; d < 6; ++d) s += e[d] * __ldg(&Ew[d * 6 + c]);
        g_me6[i * 6 + c] = s;
    }
}

__global__ void init_kernel(const float* __restrict__ h) {
    int i = blockIdx.x * blockDim.x + threadIdx.x;
    if (i >= N_NODES * HSTRIDE) return;
    int v = i / HSTRIDE, k = i % HSTRIDE;
    g_h[0][i] = (k < HDIM) ? h[v * HDIM + k] : 0.f;
}

// ---------------- per-mtile X fill: split to tf32 hi/lo in smem ----------------
__device__ __forceinline__ void fill_tile(const float* __restrict__ hin,
                                          const int* __restrict__ nbr, int j,
                                          int base, int mt,
                                          uint32_t* __restrict__ ahi,
                                          uint32_t* __restrict__ alo, int tid) {
    // 16 rows x 38 float4 chunks (152 cols): self [0,72) | gather [72,144) | me [144,152)
#pragma unroll
    for (int e = tid; e < 16 * 38; e += THREADS) {
        int r = e / 38, q = e - r * 38;
        int node = base + mt * 16 + r;
        if (node > N_NODES - 1) node = N_NODES - 1;
        float4 v;
        if (q < 18) {
            v = *(const float4*)(hin + (size_t)node * HSTRIDE + 4 * q);
        } else if (q < 36) {
            int gi = __ldg(&nbr[(size_t)node * DEG + j]);
            v = *(const float4*)(hin + (size_t)gi * HSTRIDE + 4 * (q - 18));
        } else {
            const float* me = g_me6 + ((size_t)node * DEG + j) * 6;
            if (q == 36) v = make_float4(me[0], me[1], me[2], me[3]);
            else         v = make_float4(me[4], me[5], 0.f, 0.f);
        }
        uint32_t h0 = cvt_tf32(v.x), h1 = cvt_tf32(v.y), h2 = cvt_tf32(v.z), h3 = cvt_tf32(v.w);
        uint32_t l0 = cvt_tf32(v.x - __uint_as_float(h0));
        uint32_t l1 = cvt_tf32(v.y - __uint_as_float(h1));
        uint32_t l2 = cvt_tf32(v.z - __uint_as_float(h2));
        uint32_t l3 = cvt_tf32(v.w - __uint_as_float(h3));
        int off = r * ASTRIDE + 4 * q;
        *(uint4*)(ahi + off) = make_uint4(h0, h1, h2, h3);
        *(uint4*)(alo + off) = make_uint4(l0, l1, l2, l3);
    }
}

// ---------------- one MP step on tensor cores (mma.sync tf32, 3xTF32) ----------------
__global__ __launch_bounds__(THREADS, 2)
void step_kernel(const int* __restrict__ nbr, int j, int src) {
    __shared__ uint32_t sAhi[2][16 * ASTRIDE];
    __shared__ uint32_t sAlo[2][16 * ASTRIDE];

    const float* __restrict__ hin = g_h[src];
    float* __restrict__ hout = g_h[src ^ 1];
    int tid = threadIdx.x, w = tid >> 5, lane = tid & 31;
    int base = blockIdx.x * BM;

    // B fragments for this warp's 8-column strip: 76 registers
    uint32_t Bhi[NKT][2], Blo[NKT][2];
#pragma unroll
    for (int kt = 0; kt < NKT; ++kt)
#pragma unroll
        for (int r = 0; r < 2; ++r) {
            int idx = ((w * NKT + kt) * 2 + r) * 32 + lane;
            Bhi[kt][r] = g_Bfhi[idx];
            Blo[kt][r] = g_Bflo[idx];
        }
    int col = w * 8 + (lane & 3) * 2;
    float bb0 = g_btot[col], bb1 = g_btot[col + 1];

    fill_tile(hin, nbr, j, base, 0, sAhi[0], sAlo[0], tid);
    __syncthreads();

#pragma unroll 1
    for (int mt = 0; mt < BMT; ++mt) {
        // prefetch next tile (issues global loads early; writes the other buffer)
        if (mt < BMT - 1)
            fill_tile(hin, nbr, j, base, mt + 1, sAhi[(mt + 1) & 1], sAlo[(mt + 1) & 1], tid);

        // compute current tile
        const uint32_t* ah = sAhi[mt & 1];
        const uint32_t* al = sAlo[mt & 1];
        float c0 = 0.f, c1 = 0.f, c2 = 0.f, c3 = 0.f;
        int ra = (lane >> 2) * ASTRIDE + (lane & 3);
#pragma unroll
        for (int kt = 0; kt < NKT; ++kt) {
            int o = ra + kt * 8;
            uint32_t a0 = ah[o],     a1 = ah[o + 8 * ASTRIDE];
            uint32_t a2 = ah[o + 4], a3 = ah[o + 8 * ASTRIDE + 4];
            MMA4(c0, c1, c2, c3, a0, a1, a2, a3, Bhi[kt][0], Bhi[kt][1]);
            MMA4(c0, c1, c2, c3, a0, a1, a2, a3, Blo[kt][0], Blo[kt][1]);
            uint32_t l0 = al[o],     l1 = al[o + 8 * ASTRIDE];
            uint32_t l2 = al[o + 4], l3 = al[o + 8 * ASTRIDE + 4];
            MMA4(c0, c1, c2, c3, l0, l1, l2, l3, Bhi[kt][0], Bhi[kt][1]);
        }

        // epilogue: bias + relu, store two float2 per thread
        int row = lane >> 2;
        int node0 = base + mt * 16 + row;
        if (node0 < N_NODES) {
            float2 o;
            o.x = fmaxf(c0 + bb0, 0.f);
            o.y = fmaxf(c1 + bb1, 0.f);
            *(float2*)(hout + (size_t)node0 * HSTRIDE + col) = o;
        }
        int node1 = node0 + 8;
        if (node1 < N_NODES) {
            float2 o;
            o.x = fmaxf(c2 + bb0, 0.f);
            o.y = fmaxf(c3 + bb1, 0.f);
            *(float2*)(hout + (size_t)node1 * HSTRIDE + col) = o;
        }
        __syncthreads();
    }
}

// ---------------- readout ----------------
__global__ __launch_bounds__(RTHREADS)
void readout_kernel(const float* __restrict__ Rb) {
    int k = threadIdx.x;
    float rc[HSTRIDE];
#pragma unroll
    for (int p = 0; p < HDIM; ++p) rc[p] = g_Rc[p * 128 + k];
    rc[70] = 0.f; rc[71] = 0.f;
    float rb = Rb[k];

    int per = (N_NODES + RBLOCKS - 1) / RBLOCKS;
    int n0 = blockIdx.x * per;
    int n1 = n0 + per; if (n1 > N_NODES) n1 = N_NODES;

    float acc = 0.f;
    for (int n = n0; n < n1; ++n) {
        const float4* hp = (const float4*)(g_h[0] + (size_t)n * HSTRIDE);
        float s = rb;
#pragma unroll
        for (int q = 0; q < HSTRIDE / 4; ++q) {
            float4 hv = __ldg(&hp[q]);
            s += hv.x * rc[4 * q] + hv.y * rc[4 * q + 1]
               + hv.z * rc[4 * q + 2] + hv.w * rc[4 * q + 3];
        }
        acc += fmaxf(s, 0.f);
    }
    g_partial[blockIdx.x * 128 + k] = acc;
}

__global__ void final_kernel(const float* __restrict__ S1w, const float* __restrict__ S1b,
                             const float* __restrict__ S2w, const float* __restrict__ S2b,
                             const float* __restrict__ Hw,  const float* __restrict__ Hb,
                             const float* __restrict__ Ow,  const float* __restrict__ Ob,
                             float* __restrict__ out) {
    __shared__ float fm[128], av[128], bv[100], cv[100];
    int t = threadIdx.x;
    float s = 0.f;
    for (int b = 0; b < RBLOCKS; ++b) s += g_partial[b * 128 + t];
    fm[t] = s;
    __syncthreads();
    float v = S1b[t];
    for (int p = 0; p < 128; ++p) v += fm[p] * S1w[p * 128 + t];
    av[t] = fmaxf(v, 0.f);
    __syncthreads();
    if (t < 100) {
        v = S2b[t];
        for (int p = 0; p < 128; ++p) v += av[p] * S2w[p * 100 + t];
        bv[t] = v;
    }
    __syncthreads();
    if (t < 100) {
        v = Hb[t];
        for (int p = 0; p < 100; ++p) v += bv[p] * Hw[p * 100 + t];
        cv[t] = fmaxf(v, 0.f);
    }
    __syncthreads();
    if (t == 0) {
        v = Ob[0];
        for (int p = 0; p < 100; ++p) v += cv[p] * Ow[p];
        out[0] = v;
    }
}

extern "C" void kernel_launch(void* const* d_in, const int* in_sizes, int n_in,
                              void* d_out, int out_size) {
    const float* h   = (const float*)d_in[0];
    const float* ef  = (const float*)d_in[1];
    const int*   nbr = (const int*)d_in[2];
    const float* Vw  = (const float*)d_in[3];
    const float* Vb  = (const float*)d_in[4];
    const float* Ew  = (const float*)d_in[5];
    const float* Eb  = (const float*)d_in[6];
    const float* Uw  = (const float*)d_in[7];
    const float* Ub  = (const float*)d_in[8];
    const float* Rw  = (const float*)d_in[9];
    const float* Rb  = (const float*)d_in[10];
    const float* S1w = (const float*)d_in[11];
    const float* S1b = (const float*)d_in[12];
    const float* S2w = (const float*)d_in[13];
    const float* S2b = (const float*)d_in[14];
    const float* Hw  = (const float*)d_in[15];
    const float* Hb  = (const float*)d_in[16];
    const float* Ow  = (const float*)d_in[17];
    const float* Ob  = (const float*)d_in[18];
    float* out = (float*)d_out;

    prep_kernel<<<1, 256>>>(Vw, Vb, Uw, Ub, Rw);
    edge_kernel<<<(N_NODES * DEG + 255) / 256, 256>>>(ef, Ew, Eb);
    init_kernel<<<(N_NODES * HSTRIDE + 255) / 256, 256>>>(h);

    int src = 0;
    for (int r = 0; r < T_ROUNDS; ++r) {
        for (int j = 0; j < DEG; ++j) {
            step_kernel<<<NBLK, THREADS>>>(nbr, j, src);
            src ^= 1;
        }
    }
    // 48 steps (even) -> final state in g_h[0]
    readout_kernel<<<RBLOCKS, RTHREADS>>>(Rb);
    final_kernel<<<1, 128>>>(S1w, S1b, S2w, S2b, Hw, Hb, Ow, Ob, out);
}